// round 3
// baseline (speedup 1.0000x reference)
#include <cuda_runtime.h>

// GNNTorso: R-GCN on a fixed template graph.
// Key structure exploited:
//  - all edges connect nodes within the same time frame t; output reads only t=0
//    -> compute only the 64 nodes of frame 0 (8x less work)
//  - per-relation neighborhoods are "all nodes sharing one axis, differing on another,
//    free on the third": degree is uniformly 12 and aggregation collapses to pooled sums:
//      agg0 = (A[i]  - Pij[i,j]) / 12      A[i]  = sum_{j,k} x
//      agg1 = (B[j]  - Pij[i,j]) / 12      B[j]  = sum_{i,k} x
//      agg2 = (Ck[k] - Pik[i,k]) / 12      Ck[k] = sum_{i,j} x,  Pij = sum_k, Pik = sum_j
//  - sum_r agg_r @ W_r = (A@W0 + B@W1 + Ck@W2 - Pij@(W0+W1) - Pik@W2)/12
//    (transform 44 pooled slices instead of 3 matvecs per node)

#define PADR 36   // row stride (floats) for 32-channel rows; 36*4B=144B (16B aligned, bank-staggered)

// shared layout (float offsets)
constexpr int OW0   = 0;                 // 1024
constexpr int OW1   = 1024;
constexpr int OW2   = 2048;
constexpr int OW01  = 3072;              // W0 + W1
constexpr int OWR   = 4096;              // conv_root[l]
constexpr int OX    = 5120;              // xsh: 64 * 36 = 2304
constexpr int OPIJ  = 7424;              // 16 * 36
constexpr int OPIK  = 8000;
constexpr int OA    = 8576;              // 4 * 36
constexpr int OB    = 8720;
constexpr int OCK   = 8864;
constexpr int OPIJ2 = 9008;
constexpr int OPIK2 = 9584;
constexpr int OA2   = 10160;
constexpr int OB2   = 10304;
constexpr int OC2   = 10448;
constexpr int OBIAS = 10592;
constexpr int OLNG  = 10624;
constexpr int OLNB  = 10656;
constexpr int SMTOT = 10688;             // 42.75 KB static shared

__global__ __launch_bounds__(128) void gnn_torso_kernel(
    const float* __restrict__ xx, const float* __restrict__ ss,
    const float* __restrict__ Wf, const float* __restrict__ bf,
    const float* __restrict__ convw, const float* __restrict__ convroot,
    const float* __restrict__ convbias, const float* __restrict__ lngp,
    const float* __restrict__ lnbp, float* __restrict__ out)
{
    __shared__ __align__(16) float sm[SMTOT];

    const int tid  = threadIdx.x;
    const int b    = blockIdx.x;
    const int n    = tid >> 1;        // node 0..63 (i*16 + j*4 + k), frame t=0
    const int half = tid & 1;         // channel half
    const int c0   = half * 16;
    const int ni = n >> 4, nj = (n >> 2) & 3, nk = n & 3;

    // stage LayerNorm params once
    if (tid < 32) { sm[OLNG + tid] = lngp[tid]; sm[OLNB + tid] = lnbp[tid]; }

    // ---- input features: feats = [i/3, j/3, k/3, t/7(=0), v, m] @ W_f + b_f ----
    float x[16];
    {
        const float fi = ni * (1.0f / 3.0f);
        const float fj = nj * (1.0f / 3.0f);
        const float fk = nk * (1.0f / 3.0f);
        const float v  = xx[b * 512 + n];          // xx[b, t=0, i, j, k]
        const float m  = ss[b] * 0.125f;           // ss[b,0] / T
#pragma unroll
        for (int q = 0; q < 16; q++) {
            const int c = c0 + q;
            x[q] = bf[c] + fi * Wf[c] + fj * Wf[32 + c] + fk * Wf[64 + c]
                 + v * Wf[128 + c] + m * Wf[160 + c];
        }
    }

    for (int l = 0; l < 4; l++) {
        __syncthreads();   // S0: previous-layer consumers of weights/xsh are done

        // ---- stage this layer's weights; write x -> xsh ----
        {
            const float4* cw = (const float4*)(convw + l * 3072);
            const float4* cr = (const float4*)(convroot + l * 1024);
#pragma unroll
            for (int u = tid; u < 256; u += 128) {
                float4 a0 = cw[u], a1 = cw[256 + u], a2 = cw[512 + u], rr = cr[u];
                ((float4*)(sm + OW0))[u] = a0;
                ((float4*)(sm + OW1))[u] = a1;
                ((float4*)(sm + OW2))[u] = a2;
                ((float4*)(sm + OW01))[u] =
                    make_float4(a0.x + a1.x, a0.y + a1.y, a0.z + a1.z, a0.w + a1.w);
                ((float4*)(sm + OWR))[u] = rr;
            }
            if (tid < 32) sm[OBIAS + tid] = convbias[l * 32 + tid];
#pragma unroll
            for (int q = 0; q < 4; q++)
                *(float4*)&sm[OX + n * PADR + c0 + q * 4] =
                    make_float4(x[q * 4], x[q * 4 + 1], x[q * 4 + 2], x[q * 4 + 3]);
        }
        __syncthreads();   // S1

        // ---- P1: Pij[i,j] = sum_k x ;  Pik[i,k] = sum_j x ----
#pragma unroll
        for (int pass = 0; pass < 2; pass++) {
            const int tau = tid;
            const int sl = (tau >> 3) & 15;
            const int cg = tau & 7;
            const int i_ = sl >> 2, o_ = sl & 3;
            const int base   = (pass == 0) ? (i_ * 16 + o_ * 4) : (i_ * 16 + o_);
            const int stride = (pass == 0) ? 1 : 4;
            float4 acc = make_float4(0.f, 0.f, 0.f, 0.f);
#pragma unroll
            for (int q = 0; q < 4; q++) {
                const float4 v = *(const float4*)&sm[OX + (base + q * stride) * PADR + cg * 4];
                acc.x += v.x; acc.y += v.y; acc.z += v.z; acc.w += v.w;
            }
            *(float4*)&sm[((pass == 0) ? OPIJ : OPIK) + sl * PADR + cg * 4] = acc;
        }
        __syncthreads();   // S2

        // ---- P2: A[i]=sum_j Pij, B[j]=sum_i Pij, Ck[k]=sum_i Pik ----
        if (tid < 96) {
            const int kind = tid >> 5, r = (tid >> 3) & 3, cg = tid & 7;
            int srcb, base, stride, dsto;
            if (kind == 0)      { srcb = OPIJ; base = r * 4; stride = 1; dsto = OA;  }
            else if (kind == 1) { srcb = OPIJ; base = r;     stride = 4; dsto = OB;  }
            else                { srcb = OPIK; base = r;     stride = 4; dsto = OCK; }
            float4 acc = make_float4(0.f, 0.f, 0.f, 0.f);
#pragma unroll
            for (int q = 0; q < 4; q++) {
                const float4 v = *(const float4*)&sm[srcb + (base + q * stride) * PADR + cg * 4];
                acc.x += v.x; acc.y += v.y; acc.z += v.z; acc.w += v.w;
            }
            *(float4*)&sm[dsto + r * PADR + cg * 4] = acc;
        }
        __syncthreads();   // S3

        // ---- P3: transform pooled sums: 44 slices x 32 couts (vec4 units) ----
        for (int tau = tid; tau < 352; tau += 128) {
            const int sl = tau >> 3, cg = tau & 7;
            int srco, wo, dsto;
            if (sl < 16)      { srco = OPIJ + sl * PADR;        wo = OW01; dsto = OPIJ2 + sl * PADR; }
            else if (sl < 32) { srco = OPIK + (sl - 16) * PADR; wo = OW2;  dsto = OPIK2 + (sl - 16) * PADR; }
            else if (sl < 36) { srco = OA + (sl - 32) * PADR;   wo = OW0;  dsto = OA2 + (sl - 32) * PADR; }
            else if (sl < 40) { srco = OB + (sl - 36) * PADR;   wo = OW1;  dsto = OB2 + (sl - 36) * PADR; }
            else              { srco = OCK + (sl - 40) * PADR;  wo = OW2;  dsto = OC2 + (sl - 40) * PADR; }
            float sv[32];
#pragma unroll
            for (int q = 0; q < 8; q++) {
                const float4 t = *(const float4*)&sm[srco + q * 4];
                sv[q * 4] = t.x; sv[q * 4 + 1] = t.y; sv[q * 4 + 2] = t.z; sv[q * 4 + 3] = t.w;
            }
            float4 acc = make_float4(0.f, 0.f, 0.f, 0.f);
#pragma unroll
            for (int ci = 0; ci < 32; ci++) {
                const float4 w = *(const float4*)&sm[wo + ci * 32 + cg * 4];
                acc.x = fmaf(sv[ci], w.x, acc.x);
                acc.y = fmaf(sv[ci], w.y, acc.y);
                acc.z = fmaf(sv[ci], w.z, acc.z);
                acc.w = fmaf(sv[ci], w.w, acc.w);
            }
            *(float4*)&sm[dsto + cg * 4] = acc;
        }
        __syncthreads();   // S4

        // ---- P4: h = x@root + bias + comb/12 ; relu ; layernorm ----
        float h[16];
        {
            const float inv12 = 1.0f / 12.0f;
#pragma unroll
            for (int q = 0; q < 4; q++) {
                const int c = c0 + q * 4;
                const float4 bv = *(const float4*)&sm[OBIAS + c];
                const float4 av = *(const float4*)&sm[OA2 + ni * PADR + c];
                const float4 bb = *(const float4*)&sm[OB2 + nj * PADR + c];
                const float4 cv = *(const float4*)&sm[OC2 + nk * PADR + c];
                const float4 pv = *(const float4*)&sm[OPIJ2 + (ni * 4 + nj) * PADR + c];
                const float4 qv = *(const float4*)&sm[OPIK2 + (ni * 4 + nk) * PADR + c];
                h[q * 4 + 0] = bv.x + (av.x + bb.x + cv.x - pv.x - qv.x) * inv12;
                h[q * 4 + 1] = bv.y + (av.y + bb.y + cv.y - pv.y - qv.y) * inv12;
                h[q * 4 + 2] = bv.z + (av.z + bb.z + cv.z - pv.z - qv.z) * inv12;
                h[q * 4 + 3] = bv.w + (av.w + bb.w + cv.w - pv.w - qv.w) * inv12;
            }
        }
#pragma unroll
        for (int ci = 0; ci < 32; ci++) {
            const float xv = sm[OX + n * PADR + ci];
#pragma unroll
            for (int q = 0; q < 4; q++) {
                const float4 w = *(const float4*)&sm[OWR + ci * 32 + c0 + q * 4];
                h[q * 4 + 0] = fmaf(xv, w.x, h[q * 4 + 0]);
                h[q * 4 + 1] = fmaf(xv, w.y, h[q * 4 + 1]);
                h[q * 4 + 2] = fmaf(xv, w.z, h[q * 4 + 2]);
                h[q * 4 + 3] = fmaf(xv, w.w, h[q * 4 + 3]);
            }
        }
        // relu + two-pass layernorm over 32 channels (pairs of threads share a node)
        float s1 = 0.f;
#pragma unroll
        for (int q = 0; q < 16; q++) { h[q] = fmaxf(h[q], 0.f); s1 += h[q]; }
        s1 += __shfl_xor_sync(0xffffffffu, s1, 1);
        const float mu = s1 * (1.0f / 32.0f);
        float s2 = 0.f;
#pragma unroll
        for (int q = 0; q < 16; q++) { const float d = h[q] - mu; s2 += d * d; }
        s2 += __shfl_xor_sync(0xffffffffu, s2, 1);
        const float rs = rsqrtf(s2 * (1.0f / 32.0f) + 1e-5f);
#pragma unroll
        for (int q = 0; q < 16; q++) {
            const int c = c0 + q;
            x[q] = (h[q] - mu) * rs * sm[OLNG + c] + sm[OLNB + c];
        }
    }

    // ---- output: axis means of H0, rows: [mean_i (j,k)] [mean_j (i,k)] [mean_k (i,j)] ----
    __syncthreads();
#pragma unroll
    for (int q = 0; q < 4; q++)
        *(float4*)&sm[OX + n * PADR + c0 + q * 4] =
            make_float4(x[q * 4], x[q * 4 + 1], x[q * 4 + 2], x[q * 4 + 3]);
    __syncthreads();

    for (int tau = tid; tau < 384; tau += 128) {
        const int row = tau >> 3, cg = tau & 7;
        const int g = row >> 4, r = row & 15, a = r >> 2, d = r & 3;
        int base, stride;
        if (g == 0)      { base = a * 4 + d;      stride = 16; }  // mean over i, row=(j,k)
        else if (g == 1) { base = a * 16 + d;     stride = 4;  }  // mean over j, row=(i,k)
        else             { base = a * 16 + d * 4; stride = 1;  }  // mean over k, row=(i,j)
        float4 acc = make_float4(0.f, 0.f, 0.f, 0.f);
#pragma unroll
        for (int q = 0; q < 4; q++) {
            const float4 v = *(const float4*)&sm[OX + (base + q * stride) * PADR + cg * 4];
            acc.x += v.x; acc.y += v.y; acc.z += v.z; acc.w += v.w;
        }
        acc.x *= 0.25f; acc.y *= 0.25f; acc.z *= 0.25f; acc.w *= 0.25f;
        *(float4*)&out[b * 1536 + row * 32 + cg * 4] = acc;
    }
}

extern "C" void kernel_launch(void* const* d_in, const int* in_sizes, int n_in,
                              void* d_out, int out_size) {
    const float* xx = (const float*)d_in[0];
    const float* ss = (const float*)d_in[1];
    const float* Wf = (const float*)d_in[2];
    const float* bf = (const float*)d_in[3];
    const float* cw = (const float*)d_in[4];
    const float* cr = (const float*)d_in[5];
    const float* cb = (const float*)d_in[6];
    const float* lg = (const float*)d_in[7];
    const float* lb = (const float*)d_in[8];
    // src (d_in[9]) / dst (d_in[10]) encode the fixed template graph; structure is
    // exploited in closed form, so they are not read.
    const int B = in_sizes[1];  // ss is (B,1) -> B elements
    gnn_torso_kernel<<<B, 128>>>(xx, ss, Wf, bf, cw, cr, cb, lg, lb, (float*)d_out);
}